// round 15
// baseline (speedup 1.0000x reference)
#include <cuda_runtime.h>

#define NN 16384
#define E_EDGES 524288
#define KNB 16
#define NSEG 2
#define JSEG (NN/NSEG)
#define JCHUNK 128

// ---------------- scratch (static device globals; no allocations) ----------------
__device__ float g_x1[NN*64];
__device__ float g_u [NN*64];
__device__ float g_v [NN*64];
__device__ float g_sq[NN];
__device__ int   g_knn[NN*KNB];
__device__ float g_pd[NSEG*NN*KNB];
__device__ int   g_pi[NSEG*NN*KNB];
__device__ int   g_ei32;   // 1 if edge_index buffer is int32, 0 if int64

// ---------------- f32x2 helpers ----------------
static __device__ __forceinline__ unsigned long long pk2(float lo, float hi){
    unsigned long long r;
    asm("mov.b64 %0, {%1,%2};" : "=l"(r) : "f"(lo), "f"(hi));
    return r;
}
static __device__ __forceinline__ void fma2(unsigned long long& acc,
                                            unsigned long long a, unsigned long long b){
    asm("fma.rn.f32x2 %0, %1, %2, %0;" : "+l"(acc) : "l"(a), "l"(b));
}
static __device__ __forceinline__ float2 upk2(unsigned long long v){
    float lo, hi;
    asm("mov.b64 {%0,%1}, %2;" : "=f"(lo), "=f"(hi) : "l"(v));
    return make_float2(lo, hi);
}

// Insert (d,j) into register-resident top-16, evicting the lexicographic max (d,idx).
static __device__ __forceinline__ void t16_insert(float (&bd)[16], int (&bi)[16],
                                                  float d, int j, float& mx, int& mxi){
    int pos = 0; float cd = bd[0]; int ci = bi[0];
#pragma unroll
    for (int t = 1; t < 16; t++){
        bool g = (bd[t] > cd) || (bd[t] == cd && bi[t] > ci);
        cd = g ? bd[t] : cd; ci = g ? bi[t] : ci; pos = g ? t : pos;
    }
#pragma unroll
    for (int t = 0; t < 16; t++) if (t == pos){ bd[t] = d; bi[t] = j; }
    cd = bd[0]; ci = bi[0];
#pragma unroll
    for (int t = 1; t < 16; t++){
        bool g = (bd[t] > cd) || (bd[t] == cd && bi[t] > ci);
        cd = g ? bd[t] : cd; ci = g ? bi[t] : ci;
    }
    mx = cd; mxi = ci;
}

// ---------------- edge_index dtype detection ----------------
__global__ void k_detect(const int* __restrict__ ei){
    __shared__ int nz;
    if (threadIdx.x == 0) nz = 0;
    __syncthreads();
    int c = 0;
    for (int t = threadIdx.x; t < 4096; t += blockDim.x)
        if (ei[2*t + 1] != 0) c = 1;
    if (c) atomicOr(&nz, 1);
    __syncthreads();
    if (threadIdx.x == 0) g_ei32 = nz;
}

// ---------------- init: zero x1 accumulator and output ----------------
__global__ void k_init(float* __restrict__ out){
    int i = blockIdx.x*blockDim.x + threadIdx.x;
    if (i < NN*64){ g_x1[i] = 0.f; out[i] = 0.f; }
}

// ---------------- per-node affine split of layer 1 ----------------
template<int CIN, bool SQ, bool FROMX1>
__global__ void __launch_bounds__(256) k_node(const float* __restrict__ xin,
                                              const float* __restrict__ W,
                                              const float* __restrict__ bias){
    __shared__ __align__(16) float sW[2*CIN*64];
    __shared__ __align__(16) float sb[64];
    for (int t = threadIdx.x; t < 2*CIN*64; t += blockDim.x) sW[t] = W[t];
    if (threadIdx.x < 64) sb[threadIdx.x] = bias[threadIdx.x];
    __syncthreads();

    int i = blockIdx.x*blockDim.x + threadIdx.x;
    const float* xb = FROMX1 ? (const float*)g_x1 : xin;
    float xr[CIN];
#pragma unroll
    for (int k = 0; k < CIN; k++) xr[k] = xb[i*CIN + k];
    if (SQ){
        float s = 0.f;
#pragma unroll
        for (int k = 0; k < CIN; k++) s += xr[k]*xr[k];
        g_sq[i] = s;
    }
    for (int cq = 0; cq < 16; cq++){
        float4 au = make_float4(0.f,0.f,0.f,0.f);
        float4 av = make_float4(0.f,0.f,0.f,0.f);
#pragma unroll
        for (int k = 0; k < CIN; k++){
            float4 wt = *(const float4*)(sW + k*64 + cq*4);
            float4 wb = *(const float4*)(sW + (CIN+k)*64 + cq*4);
            float p = xr[k];
            au.x += p*wt.x; au.y += p*wt.y; au.z += p*wt.z; au.w += p*wt.w;
            av.x += p*wb.x; av.y += p*wb.y; av.z += p*wb.z; av.w += p*wb.w;
        }
        float4 bb = *(const float4*)(sb + cq*4);
        float4 uo;
        uo.x = bb.x + au.x - av.x; uo.y = bb.y + au.y - av.y;
        uo.z = bb.z + au.z - av.z; uo.w = bb.w + au.w - av.w;
        *(float4*)(g_u + i*64 + cq*4) = uo;
        *(float4*)(g_v + i*64 + cq*4) = av;
    }
}

// ---------------- per-edge: ReLU(u+v) -> 64x64 layer-2 -> ReLU -> atomic seg-max ----------
static __device__ __forceinline__ void edge_tail(int dst, int src,
                                                 const float* __restrict__ sWt,
                                                 const float* __restrict__ sb,
                                                 float* __restrict__ outb){
    const float4* up = (const float4*)(g_u + dst*64);
    const float4* vp = (const float4*)(g_v + src*64);
    unsigned long long h1p[32];
#pragma unroll
    for (int q = 0; q < 16; q++){
        float4 a = up[q], b = vp[q];
        h1p[2*q  ] = pk2(fmaxf(a.x+b.x,0.f), fmaxf(a.y+b.y,0.f));
        h1p[2*q+1] = pk2(fmaxf(a.z+b.z,0.f), fmaxf(a.w+b.w,0.f));
    }
    int* orow = (int*)outb + dst*64;
    for (int c = 0; c < 64; c++){
        const ulonglong2* w = (const ulonglong2*)(sWt + c*64);
        unsigned long long a0 = pk2(sb[c], 0.f), a1 = 0ull, a2 = 0ull, a3 = 0ull;
#pragma unroll
        for (int q = 0; q < 16; q += 2){
            ulonglong2 w0 = w[q], w1 = w[q+1];
            fma2(a0, h1p[2*q  ], w0.x);
            fma2(a1, h1p[2*q+1], w0.y);
            fma2(a2, h1p[2*q+2], w1.x);
            fma2(a3, h1p[2*q+3], w1.y);
        }
        float2 r0 = upk2(a0), r1 = upk2(a1), r2 = upk2(a2), r3 = upk2(a3);
        float s = ((r0.x+r0.y)+(r1.x+r1.y)) + ((r2.x+r2.y)+(r3.x+r3.y));
        if (s > 0.f) atomicMax(orow + c, __float_as_int(s));  // non-negative floats: int-max == float-max
    }
}

__global__ void __launch_bounds__(256) k_ec1(const void* __restrict__ ei,
                                             const float* __restrict__ W2,
                                             const float* __restrict__ b2){
    __shared__ __align__(16) float sWt[64*64];
    __shared__ __align__(16) float sb[64];
    for (int t = threadIdx.x; t < 4096; t += blockDim.x){
        int k = t >> 6, c = t & 63;
        sWt[c*64 + k] = W2[t];                       // transpose: contiguous over k
    }
    if (threadIdx.x < 64) sb[threadIdx.x] = b2[threadIdx.x];
    __syncthreads();
    int e = blockIdx.x*blockDim.x + threadIdx.x;
    int src, dst;
    if (g_ei32){
        const int* e32 = (const int*)ei;
        src = e32[e];                    // edge_index[0] = source j
        dst = e32[E_EDGES + e];          // edge_index[1] = target i
    } else {
        const long long* e64 = (const long long*)ei;
        src = (int)e64[e];
        dst = (int)e64[E_EDGES + e];
    }
    if ((unsigned)src < NN && (unsigned)dst < NN)
        edge_tail(dst, src, sWt, sb, g_x1);
}

__global__ void __launch_bounds__(256) k_ec2(const float* __restrict__ W4,
                                             const float* __restrict__ b4,
                                             float* __restrict__ out){
    __shared__ __align__(16) float sWt[64*64];
    __shared__ __align__(16) float sb[64];
    for (int t = threadIdx.x; t < 4096; t += blockDim.x){
        int k = t >> 6, c = t & 63;
        sWt[c*64 + k] = W4[t];
    }
    if (threadIdx.x < 64) sb[threadIdx.x] = b4[threadIdx.x];
    __syncthreads();
    int e = blockIdx.x*blockDim.x + threadIdx.x;
    int dst = e >> 4;
    int src = g_knn[e];
    edge_tail(dst, src, sWt, sb, out);
}

// ---------------- kNN: 1 row/thread, jj unrolled x4 (8 indep FFMA2 chains), 1 branch per 4 j
__global__ void __launch_bounds__(128, 3) k_knn(){
    __shared__ __align__(16) float sxj[JCHUNK*64];
    __shared__ float ssq[JCHUNK];
    int tid = threadIdx.x;
    int row = blockIdx.x*128 + tid;
    int j0  = blockIdx.y*JSEG;

    unsigned long long xi[32];
    {
        const ulonglong2* xp = (const ulonglong2*)(g_x1 + row*64);
#pragma unroll
        for (int q = 0; q < 16; q++){ ulonglong2 t = xp[q]; xi[2*q] = t.x; xi[2*q+1] = t.y; }
    }
    float sqi = g_sq[row];

    float bd[16]; int bi[16];
#pragma unroll
    for (int t = 0; t < 16; t++){ bd[t] = __int_as_float(0x7f800000); bi[t] = 0x7fffffff; }
    float mx = __int_as_float(0x7f800000); int mxi = 0x7fffffff;

    for (int ch = 0; ch < JSEG; ch += JCHUNK){
        __syncthreads();
        const float4* gs = (const float4*)(g_x1 + (size_t)(j0+ch)*64);
        float4* sd = (float4*)sxj;
#pragma unroll
        for (int t = 0; t < (JCHUNK*16)/128; t++) sd[tid + t*128] = gs[tid + t*128];
        if (tid < JCHUNK) ssq[tid] = g_sq[j0 + ch + tid];
        __syncthreads();

        for (int jj = 0; jj < JCHUNK; jj += 4){
            const ulonglong2* sp0 = (const ulonglong2*)(sxj + (jj+0)*64);
            const ulonglong2* sp1 = (const ulonglong2*)(sxj + (jj+1)*64);
            const ulonglong2* sp2 = (const ulonglong2*)(sxj + (jj+2)*64);
            const ulonglong2* sp3 = (const ulonglong2*)(sxj + (jj+3)*64);
            unsigned long long a00=0ull,a01=0ull,a10=0ull,a11=0ull;
            unsigned long long a20=0ull,a21=0ull,a30=0ull,a31=0ull;
#pragma unroll
            for (int q = 0; q < 16; q++){
                unsigned long long e0 = xi[2*q], e1 = xi[2*q+1];
                ulonglong2 w0 = sp0[q]; fma2(a00, e0, w0.x); fma2(a01, e1, w0.y);
                ulonglong2 w1 = sp1[q]; fma2(a10, e0, w1.x); fma2(a11, e1, w1.y);
                ulonglong2 w2 = sp2[q]; fma2(a20, e0, w2.x); fma2(a21, e1, w2.y);
                ulonglong2 w3 = sp3[q]; fma2(a30, e0, w3.x); fma2(a31, e1, w3.y);
            }
            float2 p0a = upk2(a00), p0b = upk2(a01);
            float2 p1a = upk2(a10), p1b = upk2(a11);
            float2 p2a = upk2(a20), p2b = upk2(a21);
            float2 p3a = upk2(a30), p3b = upk2(a31);
            float d0 = sqi + ssq[jj+0] - 2.f*((p0a.x+p0a.y)+(p0b.x+p0b.y));
            float d1 = sqi + ssq[jj+1] - 2.f*((p1a.x+p1a.y)+(p1b.x+p1b.y));
            float d2 = sqi + ssq[jj+2] - 2.f*((p2a.x+p2a.y)+(p2b.x+p2b.y));
            float d3 = sqi + ssq[jj+3] - 2.f*((p3a.x+p3a.y)+(p3b.x+p3b.y));
            // ascending j + strict < reproduces lax.top_k tie order exactly;
            // single branch per 4 candidates amortizes BSSY/BSYNC cost
            if ((d0 < mx) | (d1 < mx) | (d2 < mx) | (d3 < mx)){
                int j = j0 + ch + jj;
                if (d0 < mx) t16_insert(bd, bi, d0, j+0, mx, mxi);
                if (d1 < mx) t16_insert(bd, bi, d1, j+1, mx, mxi);
                if (d2 < mx) t16_insert(bd, bi, d2, j+2, mx, mxi);
                if (d3 < mx) t16_insert(bd, bi, d3, j+3, mx, mxi);
            }
        }
    }
    int base = (blockIdx.y*NN + row)*KNB;
#pragma unroll
    for (int t = 0; t < 16; t++){ g_pd[base+t] = bd[t]; g_pi[base+t] = bi[t]; }
}

// ---------------- merge per-segment top-16s into global top-16 set ----------------
__global__ void __launch_bounds__(256) k_merge(){
    int i = blockIdx.x*blockDim.x + threadIdx.x;
    float bd[16]; int bi[16];
#pragma unroll
    for (int t = 0; t < 16; t++){ bd[t] = __int_as_float(0x7f800000); bi[t] = 0x7fffffff; }
    float mx = __int_as_float(0x7f800000); int mxi = 0x7fffffff;
    for (int s = 0; s < NSEG; s++){
        int base = (s*NN + i)*KNB;
#pragma unroll
        for (int t = 0; t < 16; t++){
            float d = g_pd[base+t]; int j = g_pi[base+t];
            if (d < mx || (d == mx && j < mxi)){
                t16_insert(bd, bi, d, j, mx, mxi);
            }
        }
    }
#pragma unroll
    for (int t = 0; t < 16; t++) g_knn[i*KNB + t] = bi[t];
}

// ---------------- launch ----------------
extern "C" void kernel_launch(void* const* d_in, const int* in_sizes, int n_in,
                              void* d_out, int out_size){
    const float* x  = (const float*)d_in[0];
    const void*  ei = d_in[1];
    int off = (n_in > 2 && in_sizes[2] == 1) ? 3 : 2;
    const float* W1 = (const float*)d_in[off+0];
    const float* b1 = (const float*)d_in[off+1];
    const float* W2 = (const float*)d_in[off+2];
    const float* b2 = (const float*)d_in[off+3];
    const float* W3 = (const float*)d_in[off+4];
    const float* b3 = (const float*)d_in[off+5];
    const float* W4 = (const float*)d_in[off+6];
    const float* b4 = (const float*)d_in[off+7];
    float* out = (float*)d_out;

    k_detect<<<1, 256>>>((const int*)ei);
    k_init<<<(NN*64)/256, 256>>>(out);
    // EdgeConv1
    k_node<3, false, false><<<NN/256, 256>>>(x, W1, b1);
    k_ec1<<<E_EDGES/256, 256>>>(ei, W2, b2);
    // node-level work for EdgeConv2 layer-1 + sq-norms of x1 for kNN
    k_node<64, true, true><<<NN/256, 256>>>(nullptr, W3, b3);
    // kNN in x1 feature space (1 row/thread, jj unrolled x4)
    dim3 kg(NN/128, NSEG);
    k_knn<<<kg, 128>>>();
    k_merge<<<NN/256, 256>>>();
    // EdgeConv2
    k_ec2<<<(NN*KNB)/256, 256>>>(W4, b4, out);
    (void)in_sizes; (void)n_in; (void)out_size;
}

// round 16
// speedup vs baseline: 1.1967x; 1.1967x over previous
#include <cuda_runtime.h>

#define NN 16384
#define E_EDGES 524288
#define KNB 16
#define NSEG 4
#define JSEG (NN/NSEG)
#define JCHUNK 64

// ---------------- scratch (static device globals; no allocations) ----------------
__device__ float g_x1[NN*64];
__device__ float g_u [NN*64];
__device__ float g_v [NN*64];
__device__ float g_sq[NN];
__device__ int   g_knn[NN*KNB];
__device__ float g_pd[NSEG*NN*KNB];
__device__ int   g_pi[NSEG*NN*KNB];
__device__ int   g_ei32;   // 1 if edge_index buffer is int32, 0 if int64

// ---------------- f32x2 helpers ----------------
static __device__ __forceinline__ unsigned long long pk2(float lo, float hi){
    unsigned long long r;
    asm("mov.b64 %0, {%1,%2};" : "=l"(r) : "f"(lo), "f"(hi));
    return r;
}
static __device__ __forceinline__ void fma2(unsigned long long& acc,
                                            unsigned long long a, unsigned long long b){
    asm("fma.rn.f32x2 %0, %1, %2, %0;" : "+l"(acc) : "l"(a), "l"(b));
}
static __device__ __forceinline__ float2 upk2(unsigned long long v){
    float lo, hi;
    asm("mov.b64 {%0,%1}, %2;" : "=f"(lo), "=f"(hi) : "l"(v));
    return make_float2(lo, hi);
}

// Insert (d,j) into register-resident top-16, evicting the lexicographic max (d,idx).
static __device__ __forceinline__ void t16_insert(float (&bd)[16], int (&bi)[16],
                                                  float d, int j, float& mx, int& mxi){
    int pos = 0; float cd = bd[0]; int ci = bi[0];
#pragma unroll
    for (int t = 1; t < 16; t++){
        bool g = (bd[t] > cd) || (bd[t] == cd && bi[t] > ci);
        cd = g ? bd[t] : cd; ci = g ? bi[t] : ci; pos = g ? t : pos;
    }
#pragma unroll
    for (int t = 0; t < 16; t++) if (t == pos){ bd[t] = d; bi[t] = j; }
    cd = bd[0]; ci = bi[0];
#pragma unroll
    for (int t = 1; t < 16; t++){
        bool g = (bd[t] > cd) || (bd[t] == cd && bi[t] > ci);
        cd = g ? bd[t] : cd; ci = g ? bi[t] : ci;
    }
    mx = cd; mxi = ci;
}

// Shared-memory top-16 insert: write over slot mxp, rescan for new lexicographic max.
// Layout [16][128]: lane-private column -> bank tid%32, conflict-free.
static __device__ __forceinline__ void t16s_insert(float* __restrict__ sbd,
                                                   int*   __restrict__ sbi,
                                                   float d, int j,
                                                   float& mx, int& mxi, int& mxp){
    sbd[mxp*128] = d; sbi[mxp*128] = j;
    float cd = sbd[0]; int ci = sbi[0]; int cp = 0;
#pragma unroll
    for (int t = 1; t < 16; t++){
        float bt = sbd[t*128]; int it = sbi[t*128];
        bool g = (bt > cd) || (bt == cd && it > ci);
        cd = g ? bt : cd; ci = g ? it : ci; cp = g ? t : cp;
    }
    mx = cd; mxi = ci; mxp = cp;
}

// ---------------- edge_index dtype detection ----------------
__global__ void k_detect(const int* __restrict__ ei){
    __shared__ int nz;
    if (threadIdx.x == 0) nz = 0;
    __syncthreads();
    int c = 0;
    for (int t = threadIdx.x; t < 4096; t += blockDim.x)
        if (ei[2*t + 1] != 0) c = 1;
    if (c) atomicOr(&nz, 1);
    __syncthreads();
    if (threadIdx.x == 0) g_ei32 = nz;
}

// ---------------- init: zero x1 accumulator and output ----------------
__global__ void k_init(float* __restrict__ out){
    int i = blockIdx.x*blockDim.x + threadIdx.x;
    if (i < NN*64){ g_x1[i] = 0.f; out[i] = 0.f; }
}

// ---------------- per-node affine split of layer 1 ----------------
template<int CIN, bool SQ, bool FROMX1>
__global__ void __launch_bounds__(256) k_node(const float* __restrict__ xin,
                                              const float* __restrict__ W,
                                              const float* __restrict__ bias){
    __shared__ __align__(16) float sW[2*CIN*64];
    __shared__ __align__(16) float sb[64];
    for (int t = threadIdx.x; t < 2*CIN*64; t += blockDim.x) sW[t] = W[t];
    if (threadIdx.x < 64) sb[threadIdx.x] = bias[threadIdx.x];
    __syncthreads();

    int i = blockIdx.x*blockDim.x + threadIdx.x;
    const float* xb = FROMX1 ? (const float*)g_x1 : xin;
    float xr[CIN];
#pragma unroll
    for (int k = 0; k < CIN; k++) xr[k] = xb[i*CIN + k];
    if (SQ){
        float s = 0.f;
#pragma unroll
        for (int k = 0; k < CIN; k++) s += xr[k]*xr[k];
        g_sq[i] = s;
    }
    for (int cq = 0; cq < 16; cq++){
        float4 au = make_float4(0.f,0.f,0.f,0.f);
        float4 av = make_float4(0.f,0.f,0.f,0.f);
#pragma unroll
        for (int k = 0; k < CIN; k++){
            float4 wt = *(const float4*)(sW + k*64 + cq*4);
            float4 wb = *(const float4*)(sW + (CIN+k)*64 + cq*4);
            float p = xr[k];
            au.x += p*wt.x; au.y += p*wt.y; au.z += p*wt.z; au.w += p*wt.w;
            av.x += p*wb.x; av.y += p*wb.y; av.z += p*wb.z; av.w += p*wb.w;
        }
        float4 bb = *(const float4*)(sb + cq*4);
        float4 uo;
        uo.x = bb.x + au.x - av.x; uo.y = bb.y + au.y - av.y;
        uo.z = bb.z + au.z - av.z; uo.w = bb.w + au.w - av.w;
        *(float4*)(g_u + i*64 + cq*4) = uo;
        *(float4*)(g_v + i*64 + cq*4) = av;
    }
}

// ---------------- per-edge: ReLU(u+v) -> 64x64 layer-2 -> ReLU -> atomic seg-max ----------
static __device__ __forceinline__ void edge_tail(int dst, int src,
                                                 const float* __restrict__ sWt,
                                                 const float* __restrict__ sb,
                                                 float* __restrict__ outb){
    const float4* up = (const float4*)(g_u + dst*64);
    const float4* vp = (const float4*)(g_v + src*64);
    unsigned long long h1p[32];
#pragma unroll
    for (int q = 0; q < 16; q++){
        float4 a = up[q], b = vp[q];
        h1p[2*q  ] = pk2(fmaxf(a.x+b.x,0.f), fmaxf(a.y+b.y,0.f));
        h1p[2*q+1] = pk2(fmaxf(a.z+b.z,0.f), fmaxf(a.w+b.w,0.f));
    }
    int* orow = (int*)outb + dst*64;
    for (int c = 0; c < 64; c++){
        const ulonglong2* w = (const ulonglong2*)(sWt + c*64);
        unsigned long long a0 = pk2(sb[c], 0.f), a1 = 0ull, a2 = 0ull, a3 = 0ull;
#pragma unroll
        for (int q = 0; q < 16; q += 2){
            ulonglong2 w0 = w[q], w1 = w[q+1];
            fma2(a0, h1p[2*q  ], w0.x);
            fma2(a1, h1p[2*q+1], w0.y);
            fma2(a2, h1p[2*q+2], w1.x);
            fma2(a3, h1p[2*q+3], w1.y);
        }
        float2 r0 = upk2(a0), r1 = upk2(a1), r2 = upk2(a2), r3 = upk2(a3);
        float s = ((r0.x+r0.y)+(r1.x+r1.y)) + ((r2.x+r2.y)+(r3.x+r3.y));
        if (s > 0.f) atomicMax(orow + c, __float_as_int(s));  // non-negative floats: int-max == float-max
    }
}

__global__ void __launch_bounds__(256) k_ec1(const void* __restrict__ ei,
                                             const float* __restrict__ W2,
                                             const float* __restrict__ b2){
    __shared__ __align__(16) float sWt[64*64];
    __shared__ __align__(16) float sb[64];
    for (int t = threadIdx.x; t < 4096; t += blockDim.x){
        int k = t >> 6, c = t & 63;
        sWt[c*64 + k] = W2[t];                       // transpose: contiguous over k
    }
    if (threadIdx.x < 64) sb[threadIdx.x] = b2[threadIdx.x];
    __syncthreads();
    int e = blockIdx.x*blockDim.x + threadIdx.x;
    int src, dst;
    if (g_ei32){
        const int* e32 = (const int*)ei;
        src = e32[e];                    // edge_index[0] = source j
        dst = e32[E_EDGES + e];          // edge_index[1] = target i
    } else {
        const long long* e64 = (const long long*)ei;
        src = (int)e64[e];
        dst = (int)e64[E_EDGES + e];
    }
    if ((unsigned)src < NN && (unsigned)dst < NN)
        edge_tail(dst, src, sWt, sb, g_x1);
}

__global__ void __launch_bounds__(256) k_ec2(const float* __restrict__ W4,
                                             const float* __restrict__ b4,
                                             float* __restrict__ out){
    __shared__ __align__(16) float sWt[64*64];
    __shared__ __align__(16) float sb[64];
    for (int t = threadIdx.x; t < 4096; t += blockDim.x){
        int k = t >> 6, c = t & 63;
        sWt[c*64 + k] = W4[t];
    }
    if (threadIdx.x < 64) sb[threadIdx.x] = b4[threadIdx.x];
    __syncthreads();
    int e = blockIdx.x*blockDim.x + threadIdx.x;
    int dst = e >> 4;
    int src = g_knn[e];
    edge_tail(dst, src, sWt, sb, out);
}

// ---------------- kNN: 1 row/thread, top-16 state in shared, 4 CTAs/SM ----------------
// Regs ~90 (xi 64 + acc 8 + misc) -> no spill at the 128-reg cap; 16 warps/SM hide the
// per-j dependency chain that bound all previous variants (~290 cyc/warp-j exposed).
__global__ void __launch_bounds__(128, 4) k_knn(){
    __shared__ __align__(16) float sxj[JCHUNK*64];   // 16KB
    __shared__ float ssq[JCHUNK];
    __shared__ float sbd[16*128];                    // 8KB  [slot][tid]
    __shared__ int   sbi[16*128];                    // 8KB
    int tid = threadIdx.x;
    int row = blockIdx.x*128 + tid;
    int j0  = blockIdx.y*JSEG;

    unsigned long long xi[32];
    {
        const ulonglong2* xp = (const ulonglong2*)(g_x1 + row*64);
#pragma unroll
        for (int q = 0; q < 16; q++){ ulonglong2 t = xp[q]; xi[2*q] = t.x; xi[2*q+1] = t.y; }
    }
    float sqi = g_sq[row];

    float* myd = sbd + tid;
    int*   myi = sbi + tid;
#pragma unroll
    for (int t = 0; t < 16; t++){
        myd[t*128] = __int_as_float(0x7f800000);
        myi[t*128] = 0x7fffffff;
    }
    float mx = __int_as_float(0x7f800000); int mxi = 0x7fffffff; int mxp = 0;

    for (int ch = 0; ch < JSEG; ch += JCHUNK){
        __syncthreads();
        const float4* gs = (const float4*)(g_x1 + (size_t)(j0+ch)*64);
        float4* sd = (float4*)sxj;
#pragma unroll
        for (int t = 0; t < (JCHUNK*16)/128; t++) sd[tid + t*128] = gs[tid + t*128];
        if (tid < JCHUNK) ssq[tid] = g_sq[j0 + ch + tid];
        __syncthreads();

        for (int jj = 0; jj < JCHUNK; jj++){
            const ulonglong2* sp = (const ulonglong2*)(sxj + jj*64);
            unsigned long long a0 = 0ull, a1 = 0ull, a2 = 0ull, a3 = 0ull;
#pragma unroll
            for (int q = 0; q < 16; q += 2){
                ulonglong2 w0 = sp[q], w1 = sp[q+1];
                fma2(a0, xi[2*q  ], w0.x);
                fma2(a1, xi[2*q+1], w0.y);
                fma2(a2, xi[2*q+2], w1.x);
                fma2(a3, xi[2*q+3], w1.y);
            }
            float2 r0 = upk2(a0), r1 = upk2(a1), r2 = upk2(a2), r3 = upk2(a3);
            float dot = ((r0.x+r0.y)+(r1.x+r1.y)) + ((r2.x+r2.y)+(r3.x+r3.y));
            float d = sqi + ssq[jj] - 2.f*dot;
            // ascending j + strict < reproduces lax.top_k tie order exactly
            if (d < mx){
                t16s_insert(myd, myi, d, j0 + ch + jj, mx, mxi, mxp);
            }
        }
    }
    int base = (blockIdx.y*NN + row)*KNB;
#pragma unroll
    for (int t = 0; t < 16; t++){ g_pd[base+t] = myd[t*128]; g_pi[base+t] = myi[t*128]; }
}

// ---------------- merge per-segment top-16s into global top-16 set ----------------
__global__ void __launch_bounds__(256) k_merge(){
    int i = blockIdx.x*blockDim.x + threadIdx.x;
    float bd[16]; int bi[16];
#pragma unroll
    for (int t = 0; t < 16; t++){ bd[t] = __int_as_float(0x7f800000); bi[t] = 0x7fffffff; }
    float mx = __int_as_float(0x7f800000); int mxi = 0x7fffffff;
    for (int s = 0; s < NSEG; s++){
        int base = (s*NN + i)*KNB;
#pragma unroll
        for (int t = 0; t < 16; t++){
            float d = g_pd[base+t]; int j = g_pi[base+t];
            if (d < mx || (d == mx && j < mxi)){
                t16_insert(bd, bi, d, j, mx, mxi);
            }
        }
    }
#pragma unroll
    for (int t = 0; t < 16; t++) g_knn[i*KNB + t] = bi[t];
}

// ---------------- launch ----------------
extern "C" void kernel_launch(void* const* d_in, const int* in_sizes, int n_in,
                              void* d_out, int out_size){
    const float* x  = (const float*)d_in[0];
    const void*  ei = d_in[1];
    int off = (n_in > 2 && in_sizes[2] == 1) ? 3 : 2;
    const float* W1 = (const float*)d_in[off+0];
    const float* b1 = (const float*)d_in[off+1];
    const float* W2 = (const float*)d_in[off+2];
    const float* b2 = (const float*)d_in[off+3];
    const float* W3 = (const float*)d_in[off+4];
    const float* b3 = (const float*)d_in[off+5];
    const float* W4 = (const float*)d_in[off+6];
    const float* b4 = (const float*)d_in[off+7];
    float* out = (float*)d_out;

    k_detect<<<1, 256>>>((const int*)ei);
    k_init<<<(NN*64)/256, 256>>>(out);
    // EdgeConv1
    k_node<3, false, false><<<NN/256, 256>>>(x, W1, b1);
    k_ec1<<<E_EDGES/256, 256>>>(ei, W2, b2);
    // node-level work for EdgeConv2 layer-1 + sq-norms of x1 for kNN
    k_node<64, true, true><<<NN/256, 256>>>(nullptr, W3, b3);
    // kNN in x1 feature space (1 row/thread, shared-memory top-16, 4 CTAs/SM)
    dim3 kg(NN/128, NSEG);
    k_knn<<<kg, 128>>>();
    k_merge<<<NN/256, 256>>>();
    // EdgeConv2
    k_ec2<<<(NN*KNB)/256, 256>>>(W4, b4, out);
    (void)in_sizes; (void)n_in; (void)out_size;
}